// round 14
// baseline (speedup 1.0000x reference)
#include <cuda_runtime.h>
#include <cuda_bf16.h>
#include <math.h>

#define BB 32
#define TT 512
#define EPROJS 512
#define DUNITS 1024
#define ODIM 10000
#define ATT_DIM 320
#define LL 128
#define LP1 129
#define NTOK (LP1*BB)
#define SOS_EOS (ODIM-1)

__device__ __align__(16) float g_preenc[BB*TT*ATT_DIM];   // [b][t][a]
__device__ __align__(16) float g_eys[LP1*BB*DUNITS];
__device__ __align__(16) float g_zs[LP1*BB*DUNITS];
__device__ __align__(16) float g_xcat[BB*1536];
__device__ __align__(16) float g_z0[2][BB*DUNITS];
__device__ __align__(16) float g_c0[2][BB*DUNITS];
__device__ __align__(16) float g_z1[2][BB*DUNITS];
__device__ __align__(16) float g_c1[2][BB*DUNITS];
__device__ __align__(16) float g_logits[(long)NTOK*ODIM];
__device__ float g_nll[NTOK];
__device__ float g_cor[NTOK];

__device__ __forceinline__ float sigf(float x) { return 1.0f / (1.0f + expf(-x)); }

__global__ void init_state() {
    int i = blockIdx.x * 256 + threadIdx.x;
    if (i < BB * DUNITS) {
        g_z0[0][i] = 0.f; g_c0[0][i] = 0.f;
        g_z1[0][i] = 0.f; g_c1[0][i] = 0.f;
    }
}

__global__ void embed_kernel(const float* __restrict__ embed_w, const int* __restrict__ ys_pad) {
    int idx = blockIdx.x * 256 + threadIdx.x;
    if (idx >= LP1 * BB * DUNITS) return;
    int d  = idx & (DUNITS - 1);
    int rb = idx >> 10;
    int b  = rb & 31;
    int l  = rb >> 5;
    int tok = (l == 0) ? SOS_EOS : ys_pad[b * LL + (l - 1)];
    g_eys[idx] = embed_w[(long)tok * DUNITS + d];
}

// ---------------- pre_enc SGEMM: C[M,N] = A[M,K]*B[N,K]^T, tanh+bias ----------------
#define SG_BM 64
#define SG_BN 64
#define SG_BK 16
__global__ __launch_bounds__(256) void sgemm_tn(
    const float* __restrict__ Aopt, const float* __restrict__ Bm,
    int M, int N, int K, long sA, long sC,
    const float* __restrict__ biasN)
{
    const float* A = Aopt + (long)blockIdx.z * sA;
    const float* B = Bm;
    float* C = g_preenc + (long)blockIdx.z * sC;

    int m0 = blockIdx.y * SG_BM, n0 = blockIdx.x * SG_BN;
    __shared__ float As[SG_BK][SG_BM + 4];
    __shared__ float Bs[SG_BK][SG_BN + 4];
    int tid = threadIdx.x;
    int ty = tid >> 4, tx = tid & 15;
    int lr = tid >> 2;
    int lk = (tid & 3) * 4;
    float acc[4][4];
#pragma unroll
    for (int i = 0; i < 4; i++)
#pragma unroll
        for (int j = 0; j < 4; j++) acc[i][j] = 0.f;

    for (int k0 = 0; k0 < K; k0 += SG_BK) {
        float4 av = make_float4(0.f,0.f,0.f,0.f);
        int gm = m0 + lr;
        if (gm < M) av = *(const float4*)&A[(long)gm * K + k0 + lk];
        float4 bv = make_float4(0.f,0.f,0.f,0.f);
        int gn = n0 + lr;
        if (gn < N) bv = *(const float4*)&B[(long)gn * K + k0 + lk];
        __syncthreads();
        As[lk+0][lr]=av.x; As[lk+1][lr]=av.y; As[lk+2][lr]=av.z; As[lk+3][lr]=av.w;
        Bs[lk+0][lr]=bv.x; Bs[lk+1][lr]=bv.y; Bs[lk+2][lr]=bv.z; Bs[lk+3][lr]=bv.w;
        __syncthreads();
#pragma unroll
        for (int kk = 0; kk < SG_BK; kk++) {
            float4 a = *(const float4*)&As[kk][ty*4];
            float4 b = *(const float4*)&Bs[kk][tx*4];
            float aa[4] = {a.x,a.y,a.z,a.w};
            float bb[4] = {b.x,b.y,b.z,b.w};
#pragma unroll
            for (int i = 0; i < 4; i++)
#pragma unroll
                for (int j = 0; j < 4; j++) acc[i][j] += aa[i]*bb[j];
        }
    }
#pragma unroll
    for (int i = 0; i < 4; i++) {
        int row = m0 + ty*4 + i;
        if (row >= M) continue;
#pragma unroll
        for (int j = 0; j < 4; j++) {
            int col = n0 + tx*4 + j;
            if (col >= N) continue;
            C[(long)row * N + col] = tanhf(acc[i][j] + biasN[col]);
        }
    }
}

// ---------------- logits GEMM: 128x64 tile, reg prefetch, double-buffered, 1 barrier/tile ----------------
#define LG_BM 128
#define LG_BN 64
#define LG_BK 16
__global__ __launch_bounds__(256) void logits_gemm(
    const float* __restrict__ Wout, const float* __restrict__ bout)
{
    const float* A = g_zs;      // [NTOK][DUNITS]
    const float* B = Wout;      // [ODIM][DUNITS]
    int m0 = blockIdx.y * LG_BM, n0 = blockIdx.x * LG_BN;
    __shared__ float As[2][LG_BK][LG_BM + 4];
    __shared__ float Bs[2][LG_BK][LG_BN + 4];
    int tid = threadIdx.x;
    int ty = tid >> 4, tx = tid & 15;   // compute: rows ty*8..+7, cols tx*4..+3
    int lr = tid >> 2;                  // 0..63
    int lk = (tid & 3) * 4;             // 0,4,8,12
    float acc[8][4];
#pragma unroll
    for (int i = 0; i < 8; i++)
#pragma unroll
        for (int j = 0; j < 4; j++) acc[i][j] = 0.f;

    int gm0 = m0 + lr, gm1 = m0 + lr + 64, gn = n0 + lr;
    float4 av0, av1, bv;
    av0 = (gm0 < NTOK) ? *(const float4*)&A[(long)gm0 * DUNITS + lk] : make_float4(0.f,0.f,0.f,0.f);
    av1 = (gm1 < NTOK) ? *(const float4*)&A[(long)gm1 * DUNITS + lk] : make_float4(0.f,0.f,0.f,0.f);
    bv  = (gn  < ODIM) ? *(const float4*)&B[(long)gn  * DUNITS + lk] : make_float4(0.f,0.f,0.f,0.f);

    const int ntiles = DUNITS / LG_BK;   // 64
    for (int t = 0; t < ntiles; t++) {
        int buf = t & 1;
        As[buf][lk+0][lr]    = av0.x; As[buf][lk+1][lr]    = av0.y;
        As[buf][lk+2][lr]    = av0.z; As[buf][lk+3][lr]    = av0.w;
        As[buf][lk+0][lr+64] = av1.x; As[buf][lk+1][lr+64] = av1.y;
        As[buf][lk+2][lr+64] = av1.z; As[buf][lk+3][lr+64] = av1.w;
        Bs[buf][lk+0][lr] = bv.x; Bs[buf][lk+1][lr] = bv.y;
        Bs[buf][lk+2][lr] = bv.z; Bs[buf][lk+3][lr] = bv.w;
        __syncthreads();
        if (t + 1 < ntiles) {
            int k0 = (t + 1) * LG_BK;
            av0 = (gm0 < NTOK) ? *(const float4*)&A[(long)gm0 * DUNITS + k0 + lk] : make_float4(0.f,0.f,0.f,0.f);
            av1 = (gm1 < NTOK) ? *(const float4*)&A[(long)gm1 * DUNITS + k0 + lk] : make_float4(0.f,0.f,0.f,0.f);
            bv  = (gn  < ODIM) ? *(const float4*)&B[(long)gn  * DUNITS + k0 + lk] : make_float4(0.f,0.f,0.f,0.f);
        }
#pragma unroll
        for (int kk = 0; kk < LG_BK; kk++) {
            float4 a0 = *(const float4*)&As[buf][kk][ty*8];
            float4 a1 = *(const float4*)&As[buf][kk][ty*8 + 4];
            float4 b  = *(const float4*)&Bs[buf][kk][tx*4];
            float aa[8] = {a0.x,a0.y,a0.z,a0.w,a1.x,a1.y,a1.z,a1.w};
            float bb[4] = {b.x,b.y,b.z,b.w};
#pragma unroll
            for (int i = 0; i < 8; i++)
#pragma unroll
                for (int j = 0; j < 4; j++) acc[i][j] += aa[i]*bb[j];
        }
    }
#pragma unroll
    for (int i = 0; i < 8; i++) {
        int row = m0 + ty*8 + i;
        if (row >= NTOK) continue;
#pragma unroll
        for (int j = 0; j < 4; j++) {
            int col = n0 + tx*4 + j;
            if (col >= ODIM) continue;
            g_logits[(long)row * ODIM + col] = acc[i][j] + bout[col];
        }
    }
}

// ---------------- fused attention: one block per batch row, 1024 threads ----------------
__global__ __launch_bounds__(1024) void attn_fused(
    const float* __restrict__ hs, const int* __restrict__ hlens,
    const float* __restrict__ Wdec, int l, int cur)
{
    int b = blockIdx.x;
    int tid = threadIdx.x;
    int w = tid >> 5, lane = tid & 31;
    __shared__ float z0sh[DUNITS];
    __shared__ float decsh[ATT_DIM];
    __shared__ float wsh[TT];
    __shared__ float red[32];
    __shared__ float cred[EPROJS];

    z0sh[tid] = g_z0[cur][b * DUNITS + tid];
    __syncthreads();

    // dec: warp w computes rows 10w..10w+9 of tanh(z0 . Wdec^T)
    {
        const float4* zr = (const float4*)z0sh;
#pragma unroll
        for (int i = 0; i < 10; i++) {
            int a = w * 10 + i;
            const float4* wr = (const float4*)(Wdec + (long)a * DUNITS);
            float s = 0.f;
#pragma unroll
            for (int j = 0; j < 8; j++) {
                float4 wv = wr[lane + 32*j];
                float4 zv = zr[lane + 32*j];
                s += wv.x*zv.x + wv.y*zv.y + wv.z*zv.z + wv.w*zv.w;
            }
#pragma unroll
            for (int o = 16; o; o >>= 1) s += __shfl_xor_sync(0xffffffffu, s, o);
            if (lane == 0) decsh[a] = tanhf(s);
        }
    }
    __syncthreads();

    // e scores: warp w computes t = 16w..16w+15
    {
        int tl = hlens[b];
#pragma unroll
        for (int i = 0; i < 16; i++) {
            int t = w * 16 + i;
            const float* pe = g_preenc + ((long)(b * TT + t)) * ATT_DIM;
            float s = 0.f;
#pragma unroll
            for (int j = 0; j < 10; j++) s += pe[lane + 32*j] * decsh[lane + 32*j];
#pragma unroll
            for (int o = 16; o; o >>= 1) s += __shfl_xor_sync(0xffffffffu, s, o);
            if (lane == 0) wsh[t] = (t < tl) ? 2.0f * s : -1e10f;
        }
    }
    __syncthreads();

    // softmax over 512 (threads 0..511 own one element)
    float xv = 0.f;
    if (tid < TT) {
        float e = wsh[tid];
        float m = e;
#pragma unroll
        for (int o = 16; o; o >>= 1) m = fmaxf(m, __shfl_xor_sync(0xffffffffu, m, o));
        if (lane == 0) red[w] = m;
        xv = e;
    }
    __syncthreads();
    if (tid < TT) {
        float m = red[0];
#pragma unroll
        for (int q = 1; q < 16; q++) m = fmaxf(m, red[q]);
        xv = expf(xv - m);
        float s = xv;
#pragma unroll
        for (int o = 16; o; o >>= 1) s += __shfl_xor_sync(0xffffffffu, s, o);
        if (lane == 0) red[16 + w] = s;
    }
    __syncthreads();
    if (tid < TT) {
        float s = red[16];
#pragma unroll
        for (int q = 1; q < 16; q++) s += red[16 + q];
        wsh[tid] = xv / s;
    }
    // ey copy (independent of wsh)
    g_xcat[b * 1536 + tid] = g_eys[((long)l * BB + b) * DUNITS + tid];
    __syncthreads();

    // context: thread = (d = tid&511, half = tid>>9); each sums 256 t's
    {
        int d = tid & (EPROJS - 1);
        int hh = tid >> 9;
        const float* hp = hs + ((long)(b * TT) + hh * 256) * EPROJS + d;
        const float* wp = wsh + hh * 256;
        float acc = 0.f;
#pragma unroll 8
        for (int t = 0; t < 256; t++) acc += wp[t] * hp[(long)t * EPROJS];
        if (hh) cred[d] = acc;
        __syncthreads();
        if (!hh) g_xcat[b * 1536 + 1024 + d] = acc + cred[d];
    }
}

// ---------------- LSTM: 128 blocks x 256 thr; double-buffered smem, 1 barrier/tile ----------------
__global__ __launch_bounds__(256) void lstm_kernel(
    const float* __restrict__ Wih, const float* __restrict__ Whh,
    const float* __restrict__ bih, const float* __restrict__ bhh,
    int layer, int cur, int l)
{
    int nxt = cur ^ 1;
    const float* x; int ldx, nx;
    const float* h; const float* cin; float* zout; float* cout; float* zsrow = nullptr;
    if (layer == 0) {
        x = g_xcat; ldx = 1536; nx = 48;
        h = g_z0[cur]; cin = g_c0[cur]; zout = g_z0[nxt]; cout = g_c0[nxt];
    } else {
        x = g_z0[nxt]; ldx = 1024; nx = 32;
        h = g_z1[cur]; cin = g_c1[cur]; zout = g_z1[nxt]; cout = g_c1[nxt];
        zsrow = g_zs + (long)l * BB * DUNITS;
    }
    __shared__ float xs[2][32][32];
    __shared__ float ws[2][32][36];
    __shared__ float gsh[32][32];
    int tid = threadIdx.x;
    int u0 = blockIdx.x * 8;
    int r  = tid >> 3;
    int cb = (tid & 7) * 4;
    int lq = (tid & 7) * 4;
    int wrow = ((r >> 3) << 10) + u0 + (r & 7);
    float acc[4] = {0.f, 0.f, 0.f, 0.f};

    int ntot = nx + 32;
    float4 xv = *(const float4*)&x[r * ldx + lq];
    float4 wv = *(const float4*)&Wih[(long)wrow * ldx + lq];

    for (int t = 0; t < ntot; t++) {
        int buf = t & 1;
        *(float4*)&xs[buf][r][lq] = xv;
        ws[buf][lq+0][r] = wv.x; ws[buf][lq+1][r] = wv.y;
        ws[buf][lq+2][r] = wv.z; ws[buf][lq+3][r] = wv.w;
        __syncthreads();
        int tn = t + 1;
        if (tn < ntot) {
            const float* src; int sld; const float* W; int wld; int k0;
            if (tn < nx) { src = x; sld = ldx;  W = Wih; wld = ldx;  k0 = tn * 32; }
            else         { src = h; sld = 1024; W = Whh; wld = 1024; k0 = (tn - nx) * 32; }
            xv = *(const float4*)&src[r * sld + k0 + lq];
            wv = *(const float4*)&W[(long)wrow * wld + k0 + lq];
        }
#pragma unroll
        for (int k = 0; k < 32; k++) {
            float xx = xs[buf][r][k];
            float4 w4 = *(const float4*)&ws[buf][k][cb];
            acc[0] += xx * w4.x; acc[1] += xx * w4.y;
            acc[2] += xx * w4.z; acc[3] += xx * w4.w;
        }
    }
    __syncthreads();
    gsh[r][cb+0] = acc[0]; gsh[r][cb+1] = acc[1];
    gsh[r][cb+2] = acc[2]; gsh[r][cb+3] = acc[3];
    __syncthreads();
    {
        int r2 = tid >> 3, j = tid & 7, u = u0 + j;
        float ig = gsh[r2][j]      + bih[u]        + bhh[u];
        float fg = gsh[r2][8 + j]  + bih[1024 + u] + bhh[1024 + u];
        float gg = gsh[r2][16 + j] + bih[2048 + u] + bhh[2048 + u];
        float og = gsh[r2][24 + j] + bih[3072 + u] + bhh[3072 + u];
        float c2 = sigf(fg) * cin[r2 * 1024 + u] + sigf(ig) * tanhf(gg);
        float h2 = sigf(og) * tanhf(c2);
        cout[r2 * 1024 + u] = c2;
        zout[r2 * 1024 + u] = h2;
        if (zsrow) zsrow[r2 * 1024 + u] = h2;
    }
}

// ---------------- per-row softmax reduce over logits ----------------
__global__ __launch_bounds__(256) void rowred_kernel(const int* __restrict__ ys_pad) {
    int rr = blockIdx.x;
    int l = rr >> 5; int b = rr & 31;
    int tok = (l < LL) ? ys_pad[b * LL + l] : SOS_EOS;
    const float* row = g_logits + (long)rr * ODIM;
    int tid = threadIdx.x;
    __shared__ float rv[256];
    __shared__ int ri[256];

    float m = -1e30f; int mi = 0;
    for (int c = tid; c < ODIM; c += 256) {
        float v = row[c];
        if (v > m) { m = v; mi = c; }
    }
    rv[tid] = m; ri[tid] = mi;
    __syncthreads();
    for (int s = 128; s; s >>= 1) {
        if (tid < s) {
            float v2 = rv[tid+s]; int i2 = ri[tid+s];
            if (v2 > rv[tid] || (v2 == rv[tid] && i2 < ri[tid])) { rv[tid] = v2; ri[tid] = i2; }
        }
        __syncthreads();
    }
    float gm = rv[0]; int gmi = ri[0];
    __syncthreads();

    float s = 0.f;
    for (int c = tid; c < ODIM; c += 256) s += expf(row[c] - gm);
    rv[tid] = s;
    __syncthreads();
    for (int st = 128; st; st >>= 1) {
        if (tid < st) rv[tid] += rv[tid+st];
        __syncthreads();
    }
    if (tid == 0) {
        g_nll[rr] = gm + logf(rv[0]) - row[tok];
        g_cor[rr] = (gmi == tok) ? 1.f : 0.f;
    }
}

__global__ __launch_bounds__(256) void final_kernel(float* __restrict__ out) {
    __shared__ float sn[256];
    __shared__ float sc[256];
    int tid = threadIdx.x;
    float ns = 0.f, cs = 0.f;
    for (int r = tid; r < NTOK; r += 256) { ns += g_nll[r]; cs += g_cor[r]; }
    sn[tid] = ns; sc[tid] = cs;
    __syncthreads();
    for (int s = 128; s; s >>= 1) {
        if (tid < s) { sn[tid] += sn[tid+s]; sc[tid] += sc[tid+s]; }
        __syncthreads();
    }
    if (tid == 0) {
        float loss = sn[0] / (float)NTOK * (float)LL;
        out[0] = loss;
        out[1] = sc[0] / (float)NTOK;
        out[2] = expf(loss / (float)BB);
    }
}

extern "C" void kernel_launch(void* const* d_in, const int* in_sizes, int n_in,
                              void* d_out, int out_size)
{
    const float* hs     = (const float*)d_in[0];
    const int*   hlens  = (const int*)d_in[1];
    const int*   ys     = (const int*)d_in[2];
    const float* embedw = (const float*)d_in[3];
    const float* Wenc   = (const float*)d_in[4];
    const float* benc   = (const float*)d_in[5];
    const float* Wdec   = (const float*)d_in[6];
    const float* Wih0   = (const float*)d_in[7];
    const float* Whh0   = (const float*)d_in[8];
    const float* bih0   = (const float*)d_in[9];
    const float* bhh0   = (const float*)d_in[10];
    const float* Wih1   = (const float*)d_in[11];
    const float* Whh1   = (const float*)d_in[12];
    const float* bih1   = (const float*)d_in[13];
    const float* bhh1   = (const float*)d_in[14];
    const float* Wout   = (const float*)d_in[15];
    const float* bout   = (const float*)d_in[16];
    float* out = (float*)d_out;

    init_state<<<128, 256>>>();
    embed_kernel<<<(LP1 * BB * DUNITS + 255) / 256, 256>>>(embedw, ys);

    {   // pre_enc[b][t][a] = tanh(hs[b,t,:] . Wenc[a,:] + benc[a])
        dim3 g(ATT_DIM / SG_BN, TT / SG_BM, BB);
        sgemm_tn<<<g, 256>>>(hs, Wenc, TT, ATT_DIM, EPROJS,
                             (long)TT * EPROJS, (long)TT * ATT_DIM, benc);
    }

    int cur = 0;
    for (int l = 0; l < LP1; l++) {
        attn_fused<<<BB, 1024>>>(hs, hlens, Wdec, l, cur);
        lstm_kernel<<<128, 256>>>(Wih0, Whh0, bih0, bhh0, 0, cur, l);
        lstm_kernel<<<128, 256>>>(Wih1, Whh1, bih1, bhh1, 1, cur, l);
        cur ^= 1;
    }

    {   // logits = zs @ Wout^T + bout
        dim3 g((ODIM + LG_BN - 1) / LG_BN, (NTOK + LG_BM - 1) / LG_BM, 1);
        logits_gemm<<<g, 256>>>(Wout, bout);
    }
    rowred_kernel<<<NTOK, 256>>>(ys);
    final_kernel<<<1, 256>>>(out);
    (void)in_sizes; (void)n_in; (void)out_size;
}